// round 1
// baseline (speedup 1.0000x reference)
#include <cuda_runtime.h>
#include <cstdint>

// SSIM loss over NCHW (32,3,512,512) fp32 pair; 3x3 box filter, reflect pad 1,
// scalar mean output. Single fused pass: vertical 3-sum in registers (sliding
// window), horizontal 3-sum via shared memory, per-block partials reduced
// deterministically in a finalize kernel (fp64).

#define H 512
#define W 512
#define PLANES (32 * 3)
#define RPB 32                      // output rows per block
#define BLOCKS_X (H / RPB)          // 16
#define NBLOCKS (BLOCKS_X * PLANES) // 1536

__device__ float g_partials[NBLOCKS];

__device__ __forceinline__ int refl(int i) {
    // reflect pad of 1: -1 -> 1, 512 -> 510
    if (i < 0) return -i;
    if (i > H - 1) return 2 * (H - 1) - i;
    return i;
}

__global__ __launch_bounds__(512, 2)
void ssim_kernel(const float* __restrict__ x, const float* __restrict__ y) {
    const int plane = blockIdx.y;
    const int r0 = blockIdx.x * RPB;
    const int c = threadIdx.x; // 0..511

    const float* __restrict__ xp = x + (size_t)plane * H * W;
    const float* __restrict__ yp = y + (size_t)plane * H * W;

    __shared__ float sh[5][W + 2];

    const float C1 = 0.0001f;   // 0.01^2
    const float C2 = 0.0009f;   // 0.03^2
    const float inv9 = 1.0f / 9.0f;

    // register ring of the 5 quantities for rows (r-1, r)
    float p2[5], p1[5];
    {
        int rm1 = refl(r0 - 1);
        float xv = __ldg(&xp[rm1 * W + c]);
        float yv = __ldg(&yp[rm1 * W + c]);
        p2[0] = xv; p2[1] = yv; p2[2] = xv * xv; p2[3] = yv * yv; p2[4] = xv * yv;
        xv = __ldg(&xp[r0 * W + c]);
        yv = __ldg(&yp[r0 * W + c]);
        p1[0] = xv; p1[1] = yv; p1[2] = xv * xv; p1[3] = yv * yv; p1[4] = xv * yv;
    }

    float acc = 0.0f;

    for (int r = r0; r < r0 + RPB; ++r) {
        int rp1 = refl(r + 1);
        float xv = __ldg(&xp[rp1 * W + c]);
        float yv = __ldg(&yp[rp1 * W + c]);
        float cur[5];
        cur[0] = xv; cur[1] = yv; cur[2] = xv * xv; cur[3] = yv * yv; cur[4] = xv * yv;

        // vertical 3-sum for this column; write to shared with column-reflect halo
        #pragma unroll
        for (int q = 0; q < 5; ++q) {
            float v = p2[q] + p1[q] + cur[q];
            sh[q][c + 1] = v;
            if (c == 1)   sh[q][0]     = v;   // padded col -1 == col 1
            if (c == 510) sh[q][W + 1] = v;   // padded col 512 == col 510
        }
        __syncthreads();

        float s0 = sh[0][c] + sh[0][c + 1] + sh[0][c + 2];
        float s1 = sh[1][c] + sh[1][c + 1] + sh[1][c + 2];
        float s2 = sh[2][c] + sh[2][c + 1] + sh[2][c + 2];
        float s3 = sh[3][c] + sh[3][c + 1] + sh[3][c + 2];
        float s4 = sh[4][c] + sh[4][c + 1] + sh[4][c + 2];

        float mux = s0 * inv9;
        float muy = s1 * inv9;
        float sx  = s2 * inv9 - mux * mux;
        float sy  = s3 * inv9 - muy * muy;
        float sxy = s4 * inv9 - mux * muy;

        float n = (2.0f * mux * muy + C1) * (2.0f * sxy + C2);
        float d = (mux * mux + muy * muy + C1) * (sx + sy + C2);
        float v = (1.0f - n / d + 1e-20f) * 0.5f;
        v = fminf(fmaxf(v, 0.0f), 1.0f);
        acc += v;

        #pragma unroll
        for (int q = 0; q < 5; ++q) { p2[q] = p1[q]; p1[q] = cur[q]; }
        __syncthreads(); // protect shared before next row's writes
    }

    // block reduction (reuse a separate shared array)
    __shared__ float red[512];
    red[c] = acc;
    __syncthreads();
    #pragma unroll
    for (int stride = 256; stride > 0; stride >>= 1) {
        if (c < stride) red[c] += red[c + stride];
        __syncthreads();
    }
    if (c == 0) {
        g_partials[blockIdx.y * gridDim.x + blockIdx.x] = red[0];
    }
}

__global__ void finalize_kernel(float* __restrict__ out) {
    __shared__ double red[256];
    int t = threadIdx.x;
    double s = 0.0;
    for (int i = t; i < NBLOCKS; i += 256) s += (double)g_partials[i];
    red[t] = s;
    __syncthreads();
    #pragma unroll
    for (int stride = 128; stride > 0; stride >>= 1) {
        if (t < stride) red[t] += red[t + stride];
        __syncthreads();
    }
    if (t == 0) {
        const double total = (double)PLANES * H * W; // 25,165,824
        out[0] = (float)(red[0] / total);
    }
}

extern "C" void kernel_launch(void* const* d_in, const int* in_sizes, int n_in,
                              void* d_out, int out_size) {
    const float* x = (const float*)d_in[0];
    const float* y = (const float*)d_in[1];
    float* out = (float*)d_out;

    dim3 grid(BLOCKS_X, PLANES);
    ssim_kernel<<<grid, 512>>>(x, y);
    finalize_kernel<<<1, 256>>>(out);
}